// round 17
// baseline (speedup 1.0000x reference)
#include <cuda_runtime.h>
#include <cstdint>
#include <cstddef>

// ---------------------------------------------------------------------------
// Problem constants
// ---------------------------------------------------------------------------
#define DIMC   384
#define NHEADS 12
#define HD     32
#define NTOK   49
#define NWIN   64
#define BATCH  4096
#define MROWS  (BATCH * NTOK)   // 200704 = 256 * 784

// ---------------------------------------------------------------------------
// Scratch (static device globals: allocation-guard safe)
// ---------------------------------------------------------------------------
__device__ float    g_qp[(size_t)MROWS * DIMC];
__device__ float    g_kv[(size_t)MROWS * 2 * DIMC];
__device__ float    g_ao[(size_t)MROWS * DIMC];
__device__ uint32_t g_wqp[DIMC * DIMC];            // Wq  fragment-major tf32
__device__ uint32_t g_wkvp[2 * DIMC * DIMC];       // Wkv fragment-major tf32
__device__ uint32_t g_wpp[DIMC * DIMC];            // Wp  fragment-major tf32
__device__ float    g_cmb[NWIN * NHEADS * NTOK * NTOK];  // mask+bias combined

// ---------------------------------------------------------------------------
// Helpers (baseline PTX only — plain sm_103 target)
// ---------------------------------------------------------------------------
__device__ __forceinline__ uint32_t f2tf32(float x) {
    uint32_t r;
    asm("cvt.rna.tf32.f32 %0, %1;" : "=r"(r) : "f"(x));
    return r;
}

__device__ __forceinline__ void mma_tf32(float c[4], const uint32_t a[4],
                                         const uint32_t b[2]) {
    asm volatile(
        "mma.sync.aligned.m16n8k8.row.col.f32.tf32.tf32.f32 "
        "{%0,%1,%2,%3}, {%4,%5,%6,%7}, {%8,%9}, {%0,%1,%2,%3};"
        : "+f"(c[0]), "+f"(c[1]), "+f"(c[2]), "+f"(c[3])
        : "r"(a[0]), "r"(a[1]), "r"(a[2]), "r"(a[3]), "r"(b[0]), "r"(b[1]));
}

__device__ __forceinline__ uint32_t smem_u32(const void* p) {
    uint32_t a;
    asm("{ .reg .u64 t; cvta.to.shared.u64 t, %1; cvt.u32.u64 %0, t; }"
        : "=r"(a) : "l"(p));
    return a;
}

__device__ __forceinline__ void cp_async16(uint32_t dst_smem, const void* src) {
    asm volatile("cp.async.cg.shared.global [%0], [%1], 16;"
                 :: "r"(dst_smem), "l"(src) : "memory");
}
__device__ __forceinline__ void cp_commit() {
    asm volatile("cp.async.commit_group;" ::: "memory");
}

// ---------------------------------------------------------------------------
// prep_weights: W row-major [K,N] -> fragment-major tf32 global.
// Per (n-block j of 128, k-chunk c of 32): 4096-u32 image, index
//   (ng*4 + s)*64 + gb*8 + tig*2 + rb
// with ng=(n>>3)&15, gb=n&7, s=(k>>3)&3, rb=(k>>2)&1, tig=k&3.
// (unchanged from the passing R16 kernel — new tiling reads the same image)
// ---------------------------------------------------------------------------
__global__ void prep_weights(const float* __restrict__ W,
                             uint32_t* __restrict__ out, int N, int K)
{
    int t = blockIdx.x * 256 + threadIdx.x;
    if (t >= N * K) return;
    int n = t % N, k = t / N;
    uint32_t v = f2tf32(W[(size_t)k * N + n]);
    int j = n >> 7, ng = (n >> 3) & 15, gb = n & 7;
    int c = k >> 5, s = (k >> 3) & 3, rb = (k >> 2) & 1, tig = k & 3;
    int nch = K >> 5;
    out[((size_t)(j * nch + c) << 12) + (ng * 4 + s) * 64 + gb * 8 + tig * 2 + rb] = v;
}

// ---------------------------------------------------------------------------
// prep_cmb: cmb[(w*12+h)*2401 + e] = mask[w][e] + bias_table[rel[e]][h]
// ---------------------------------------------------------------------------
__global__ void prep_cmb(const float* __restrict__ mask,
                         const float* __restrict__ bias_table,
                         const int* __restrict__ rel,
                         float* __restrict__ cmb)
{
    const int NE = NTOK * NTOK;
    int t = blockIdx.x * 256 + threadIdx.x;
    if (t >= NWIN * NHEADS * NE) return;
    int e = t % NE;
    int wh = t / NE;
    int h = wh % NHEADS, w = wh / NHEADS;
    cmb[t] = mask[(size_t)w * NE + e] + bias_table[rel[e] * NHEADS + h];
}

// ---------------------------------------------------------------------------
// 3-stage cp.async pipelined TF32 tensor-core GEMM with bias:
//   C[M,N] = A[M,K] @ W^T + bias[N], weights pre-permuted (Bp).
// CTA tile 256x128, K-chunk 32, 256 threads = 8 warps as 4m x 2n of 64x64.
// Fragment smem traffic per output halved vs the 128x128 tiling ->
// tensor pipe becomes the binding resource.
// A staged raw fp32 (row-major, stride 36 u32, conflict-free frag reads);
// cvt.rna applied at fragment read. B staged as pre-permuted tf32 image.
// Requires M%256==0, N%128==0, K%32==0.
// ---------------------------------------------------------------------------
#define GBM 256
#define GBN 128
#define GBK 32
#define ASTR 36                    // u32 per A row
#define ABUFU (GBM * ASTR)         // 9216 u32 = 36 KB
#define BBUFU 4096                 // 16 KB B chunk image
#define NST 3
#define STAGEU (ABUFU + BBUFU)     // 13312 u32 = 53248 B
#define GEMM_SMEM (NST * STAGEU * 4)   // 159744 B

__global__ __launch_bounds__(256, 1) void gemm_tc(
    const float* __restrict__ A, const uint32_t* __restrict__ Bp,
    const float* __restrict__ bias, float* __restrict__ C,
    int M, int N, int K)
{
    extern __shared__ uint32_t sm[];

    const int tid  = threadIdx.x;
    const int wid  = tid >> 5;
    const int lane = tid & 31;
    const int wm   = wid & 3;      // 4 m-warps of 64 rows
    const int wn   = wid >> 2;     // 2 n-warps of 64 cols
    const int g    = lane >> 2;
    const int tig  = lane & 3;
    const int rowBase = blockIdx.y * GBM;
    const int colBase = blockIdx.x * GBN;
    const int nch = K >> 5;

    float acc[4][8][4];            // [mf][nf][reg] = 128 regs
    #pragma unroll
    for (int i = 0; i < 4; i++)
        #pragma unroll
        for (int j = 0; j < 8; j++)
            #pragma unroll
            for (int r = 0; r < 4; r++) acc[i][j][r] = 0.f;

    const float* Ag = A + (size_t)rowBase * K;
    const uint32_t* Bg = Bp + ((size_t)blockIdx.x * nch << 12);

    // issue chunk c into stage c%NST: A = 2048 x 16B (8/thread), B = 4/thread
    auto issue = [&](int c) {
        uint32_t* st = sm + (c % NST) * STAGEU;
        #pragma unroll
        for (int i = 0; i < 8; i++) {
            int f   = i * 256 + tid;        // 2048 16B chunks of A
            int row = f >> 3, c4 = f & 7;   // row 0..255, c4 0..7
            cp_async16(smem_u32(st + row * ASTR + c4 * 4),
                       Ag + (size_t)row * K + c * GBK + c4 * 4);
        }
        uint32_t bdst = smem_u32(st + ABUFU + tid * 4);
        const uint32_t* bsrc = Bg + ((size_t)c << 12) + tid * 4;
        #pragma unroll
        for (int i = 0; i < 4; i++)
            cp_async16(bdst + i * 4096, bsrc + i * 1024);
    };

    // prologue: stages 0..NST-2 in flight
    #pragma unroll
    for (int c = 0; c < NST - 1; c++) { issue(c); cp_commit(); }

    for (int c = 0; c < nch; c++) {
        asm volatile("cp.async.wait_group %0;" :: "n"(NST - 2));
        __syncthreads();                    // stage c resident for all warps
        uint32_t* Ab = sm + (c % NST) * STAGEU;
        uint32_t* Bb = Ab + ABUFU;

        // refill stage (c-1)%NST (its readers all passed the sync)
        if (c + NST - 1 < nch) issue(c + NST - 1);
        cp_commit();                        // unconditional: uniform group count

        #pragma unroll
        for (int s = 0; s < 4; s++) {
            uint32_t bf[8][2];
            #pragma unroll
            for (int nf = 0; nf < 8; nf++) {
                uint2 v = *reinterpret_cast<const uint2*>(
                    &Bb[(((wn * 8 + nf) * 4 + s) * 64) + lane * 2]);
                bf[nf][0] = v.x; bf[nf][1] = v.y;
            }
            #pragma unroll
            for (int mf = 0; mf < 4; mf++) {
                uint32_t af[4];
                int r0 = (wm * 64 + mf * 16 + g) * ASTR + s * 8 + tig;
                af[0] = f2tf32(__uint_as_float(Ab[r0]));
                af[1] = f2tf32(__uint_as_float(Ab[r0 + 8 * ASTR]));
                af[2] = f2tf32(__uint_as_float(Ab[r0 + 4]));
                af[3] = f2tf32(__uint_as_float(Ab[r0 + 8 * ASTR + 4]));
                #pragma unroll
                for (int nf = 0; nf < 8; nf++)
                    mma_tf32(acc[mf][nf], af, bf[nf]);
            }
        }
    }

    // ---- epilogue: bias add + STG.64
    #pragma unroll
    for (int nf = 0; nf < 8; nf++) {
        int col = colBase + wn * 64 + nf * 8 + tig * 2;
        float2 bv = *reinterpret_cast<const float2*>(bias + col);
        #pragma unroll
        for (int mf = 0; mf < 4; mf++) {
            int row0 = rowBase + wm * 64 + mf * 16 + g;
            float2 v0 = { acc[mf][nf][0] + bv.x, acc[mf][nf][1] + bv.y };
            float2 v1 = { acc[mf][nf][2] + bv.x, acc[mf][nf][3] + bv.y };
            *reinterpret_cast<float2*>(C + (size_t)row0 * N + col)       = v0;
            *reinterpret_cast<float2*>(C + (size_t)(row0 + 8) * N + col) = v1;
        }
    }
}

// ---------------------------------------------------------------------------
// Fused window attention v3 — register-blocked, float4-broadcast PV.
// (unchanged from the passing R16 kernel)
// ---------------------------------------------------------------------------
#define SAS 52   // sa row stride (floats); 52*4=208 B, 16B-aligned

__global__ __launch_bounds__(256) void attn_kernel(
    const float* __restrict__ qp, const float* __restrict__ kvp,
    const float* __restrict__ cmb, float* __restrict__ ao)
{
    const int b   = blockIdx.x;
    const int h   = blockIdx.y;
    const int tid = threadIdx.x;
    const int wid = tid >> 5;
    const int lane = tid & 31;

    __shared__ __align__(16) float qs[64 * 36];
    __shared__ __align__(16) float ks[64 * 36];
    __shared__ __align__(16) float vs[64 * 36];
    __shared__ __align__(16) float sa[NTOK * SAS];

    // ---- load q/k/v tiles (49 rows x 32, float4)
    for (int f = tid; f < NTOK * 8; f += 256) {
        int r = f >> 3, c4 = f & 7;
        size_t qoff  = (size_t)(b * NTOK + r) * DIMC + h * HD + c4 * 4;
        size_t kvoff = (size_t)(b * NTOK + r) * (2 * DIMC) + h * HD + c4 * 4;
        *reinterpret_cast<float4*>(qs + r * 36 + c4 * 4) =
            *reinterpret_cast<const float4*>(qp + qoff);
        *reinterpret_cast<float4*>(ks + r * 36 + c4 * 4) =
            *reinterpret_cast<const float4*>(kvp + kvoff);
        *reinterpret_cast<float4*>(vs + r * 36 + c4 * 4) =
            *reinterpret_cast<const float4*>(kvp + kvoff + DIMC);
    }
    __syncthreads();

    const float scale = 0.17677669529663687f;   // 32^{-1/2}
    const float* cb = cmb + (size_t)((b & (NWIN - 1)) * NHEADS + h) * (NTOK * NTOK);

    // ---- logits (lane caches K columns m=lane, m=lane+32 in registers)
    {
        float k0[32], k1[32];
        #pragma unroll
        for (int i = 0; i < 8; i++) {
            float4 x = *reinterpret_cast<const float4*>(ks + lane * 36 + i * 4);
            k0[i*4] = x.x; k0[i*4+1] = x.y; k0[i*4+2] = x.z; k0[i*4+3] = x.w;
            float4 y = *reinterpret_cast<const float4*>(ks + (lane + 32) * 36 + i * 4);
            k1[i*4] = y.x; k1[i*4+1] = y.y; k1[i*4+2] = y.z; k1[i*4+3] = y.w;
        }
        const bool m1ok = (lane + 32) < NTOK;
        #pragma unroll
        for (int r = 0; r < 7; r++) {
            int n = wid + 8 * r;
            if (n < NTOK) {
                float a0 = 0.f, a1 = 0.f;
                #pragma unroll
                for (int i = 0; i < 8; i++) {
                    float4 qv = *reinterpret_cast<const float4*>(qs + n * 36 + i * 4);
                    a0 = fmaf(qv.x, k0[i*4],   a0);
                    a0 = fmaf(qv.y, k0[i*4+1], a0);
                    a0 = fmaf(qv.z, k0[i*4+2], a0);
                    a0 = fmaf(qv.w, k0[i*4+3], a0);
                    a1 = fmaf(qv.x, k1[i*4],   a1);
                    a1 = fmaf(qv.y, k1[i*4+1], a1);
                    a1 = fmaf(qv.z, k1[i*4+2], a1);
                    a1 = fmaf(qv.w, k1[i*4+3], a1);
                }
                sa[n * SAS + lane] = fmaf(a0, scale, cb[n * NTOK + lane]);
                if (m1ok)
                    sa[n * SAS + lane + 32] =
                        fmaf(a1, scale, cb[n * NTOK + lane + 32]);
            }
        }
    }
    __syncthreads();

    // ---- softmax (warp-parallel per row)
    #pragma unroll
    for (int r = 0; r < 7; r++) {
        int n = wid + 8 * r;
        if (n < NTOK) {
            float x0 = sa[n * SAS + lane];
            float x1 = (lane + 32 < NTOK) ? sa[n * SAS + lane + 32] : -1e30f;
            float mx = fmaxf(x0, x1);
            #pragma unroll
            for (int o = 16; o > 0; o >>= 1)
                mx = fmaxf(mx, __shfl_xor_sync(0xFFFFFFFFu, mx, o));
            float e0 = __expf(x0 - mx);
            float e1 = (lane + 32 < NTOK) ? __expf(x1 - mx) : 0.f;
            float sum = e0 + e1;
            #pragma unroll
            for (int o = 16; o > 0; o >>= 1)
                sum += __shfl_xor_sync(0xFFFFFFFFu, sum, o);
            float inv = 1.f / sum;
            sa[n * SAS + lane] = e0 * inv;
            if (lane + 32 < NTOK) sa[n * SAS + lane + 32] = e1 * inv;
        }
    }
    __syncthreads();

    // ---- PV: lane = output channel d; m-blocks of 4, broadcast LDS.128
    {
        float accv[7];
        #pragma unroll
        for (int r = 0; r < 7; r++) accv[r] = 0.f;

        #pragma unroll
        for (int m4 = 0; m4 < 48; m4 += 4) {
            float v0 = vs[(m4 + 0) * 36 + lane];
            float v1 = vs[(m4 + 1) * 36 + lane];
            float v2 = vs[(m4 + 2) * 36 + lane];
            float v3 = vs[(m4 + 3) * 36 + lane];
            #pragma unroll
            for (int r = 0; r < 7; r++) {
                int n = wid + 8 * r;
                if (n < NTOK) {
                    float4 p = *reinterpret_cast<const float4*>(sa + n * SAS + m4);
                    accv[r] = fmaf(p.x, v0, accv[r]);
                    accv[r] = fmaf(p.y, v1, accv[r]);
                    accv[r] = fmaf(p.z, v2, accv[r]);
                    accv[r] = fmaf(p.w, v3, accv[r]);
                }
            }
        }
        {   // m = 48 remainder
            float v48 = vs[48 * 36 + lane];
            #pragma unroll
            for (int r = 0; r < 7; r++) {
                int n = wid + 8 * r;
                if (n < NTOK) accv[r] = fmaf(sa[n * SAS + 48], v48, accv[r]);
            }
        }
        #pragma unroll
        for (int r = 0; r < 7; r++) {
            int n = wid + 8 * r;
            if (n < NTOK)
                ao[(size_t)(b * NTOK + n) * DIMC + h * HD + lane] = accv[r];
        }
    }
}

// ---------------------------------------------------------------------------
// Launch
// ---------------------------------------------------------------------------
extern "C" void kernel_launch(void* const* d_in, const int* in_sizes, int n_in,
                              void* d_out, int out_size)
{
    const float* q          = (const float*)d_in[0];
    const float* kv         = (const float*)d_in[1];
    const float* mask       = (const float*)d_in[2];
    const float* Wq         = (const float*)d_in[3];
    const float* bq         = (const float*)d_in[4];
    const float* Wkv        = (const float*)d_in[5];
    const float* bkv        = (const float*)d_in[6];
    const float* Wp         = (const float*)d_in[7];
    const float* bp         = (const float*)d_in[8];
    const float* bias_table = (const float*)d_in[9];
    const int*   rel_index  = (const int*)d_in[10];
    float*       out        = (float*)d_out;

    float *qp, *kvp, *ao, *cmb;
    uint32_t *wqp, *wkvp, *wpp;
    cudaGetSymbolAddress((void**)&qp,   g_qp);
    cudaGetSymbolAddress((void**)&kvp,  g_kv);
    cudaGetSymbolAddress((void**)&ao,   g_ao);
    cudaGetSymbolAddress((void**)&wqp,  g_wqp);
    cudaGetSymbolAddress((void**)&wkvp, g_wkvp);
    cudaGetSymbolAddress((void**)&wpp,  g_wpp);
    cudaGetSymbolAddress((void**)&cmb,  g_cmb);

    cudaFuncSetAttribute(gemm_tc,
                         cudaFuncAttributeMaxDynamicSharedMemorySize, GEMM_SMEM);

    // 0. weight permutation + combined bias table
    prep_weights<<<(DIMC * DIMC + 255) / 256, 256>>>(Wq, wqp, DIMC, DIMC);
    prep_weights<<<(2 * DIMC * DIMC + 255) / 256, 256>>>(Wkv, wkvp, 2 * DIMC, DIMC);
    prep_weights<<<(DIMC * DIMC + 255) / 256, 256>>>(Wp, wpp, DIMC, DIMC);
    prep_cmb<<<(NWIN * NHEADS * NTOK * NTOK + 255) / 256, 256>>>(
        mask, bias_table, rel_index, cmb);

    const int mblocks = MROWS / GBM;   // 784

    // 1. q projection
    gemm_tc<<<dim3(DIMC / GBN, mblocks), 256, GEMM_SMEM>>>(
        q, wqp, bq, qp, MROWS, DIMC, DIMC);

    // 2. kv projection
    gemm_tc<<<dim3(2 * DIMC / GBN, mblocks), 256, GEMM_SMEM>>>(
        kv, wkvp, bkv, kvp, MROWS, 2 * DIMC, DIMC);

    // 3. fused window attention
    attn_kernel<<<dim3(BATCH, NHEADS), 256>>>(qp, kvp, cmb, ao);

    // 4. output projection
    gemm_tc<<<dim3(DIMC / GBN, mblocks), 256, GEMM_SMEM>>>(
        ao, wpp, bp, out, MROWS, DIMC, DIMC);
}